// round 6
// baseline (speedup 1.0000x reference)
#include <cuda_runtime.h>
#include <math.h>
#include <stdint.h>

// Problem dims
#define BB 128
#define SS 64
#define UU 512
#define VV 32000
#define XCC 1024   // 2U
#define G3 1536    // 3U

// Output layout: [logits (128*32000)] [state (128*512)] [alpha (128*64)]
#define STATE_OFF (BB*VV)
#define ALPHA_OFF (BB*VV + BB*UU)

// Scratch (device globals: allocation-free)
__device__ float g_E[BB*SS*UU];   // tanh(attn@W0+b0+b1)
__device__ float g_xc[BB*XCC];    // [emb gather | context]
__device__ float g_U[BB*G3];      // xc@gru_k + gru_b[0]
__device__ float g_y[BB*UU];      // relu(state@dW+db)

__device__ __forceinline__ uint32_t f2tf32(float x) {
    uint32_t r; asm("cvt.rna.tf32.f32 %0, %1;" : "=r"(r) : "f"(x)); return r;
}

__device__ __forceinline__ void mma8(float* c, const uint32_t* a, const uint32_t* b) {
    asm volatile(
        "mma.sync.aligned.m16n8k8.row.col.f32.tf32.tf32.f32 "
        "{%0,%1,%2,%3},{%4,%5,%6,%7},{%8,%9},{%0,%1,%2,%3};"
        : "+f"(c[0]), "+f"(c[1]), "+f"(c[2]), "+f"(c[3])
        : "r"(a[0]), "r"(a[1]), "r"(a[2]), "r"(a[3]),
          "r"(b[0]), "r"(b[1]));
}

// ---------------------------------------------------------------------------
// TF32 mma.sync GEMM with fragment-native SMEM layout.
// Block 128x128, BK=16, 256 threads (8 warps 2x4), warp tile 64x32.
// SMEM per buffer (16KB):
//   A region [0, 8KB): 16 tiles (mt 0..7, kt 0..1), tile = 512B,
//     value (r,k): byte = ((r>>4)*2 + (k>>3))*512 + lane*16 + reg*4
//     lane = (r&7)*4 + (k&3); reg = ((r>>3)&1) | (((k>>2)&1)<<1)
//     -> each lane's 4 a-frag regs contiguous: one LDS.128.
//   B region [8KB, 16KB): 32 tiles (nt 0..15, kt 0..1), tile = 256B,
//     value (k,n): byte = 8192 + ((n>>3)*2 + (k>>3))*256 + lane*8 + reg*4
//     lane = (n&7)*4 + (k&3); reg = (k>>2)&1
//     -> each lane's 2 b-frag regs contiguous: one LDS.64.
// Register prefetch + double buffer, one __syncthreads per chunk.
// C = epi(A[M,K]@B[K,N] + bias1 (+bias2)). EPI: 0 bias, 1 +bias2/tanh, 2 relu.
// Requires M%128==0, N%128==0, K%16==0.
// ---------------------------------------------------------------------------
template<int EPI>
__global__ __launch_bounds__(256, 2) void mma128f(
    const float* __restrict__ A, const float* __restrict__ Bm,
    float* __restrict__ C,
    const float* __restrict__ bias1, const float* __restrict__ bias2,
    int M, int N, int K)
{
    __shared__ uint32_t sm[2][4096];   // 2 x 16KB

    const int tid  = threadIdx.x;
    const int warp = tid >> 5;
    const int lane = tid & 31;
    const int bm   = blockIdx.y * 128;
    const int bn   = blockIdx.x * 128;
    const int wmt  = (warp >> 2) * 4;   // warp's first A m-tile (of 16 rows)
    const int wnt  = (warp & 3) * 4;    // warp's first B n-tile (of 8 cols)
    const int lr   = lane >> 2;
    const int lc   = lane & 3;

    // Fill assignments
    const int a_r  = tid >> 2;          // 0..63  (rows a_r and a_r+64)
    const int a_c4 = tid & 3;           // k-quad 0..3
    const int b_k  = tid >> 5;          // 0..7   (k rows b_k and b_k+8)
    const int b_nc = (tid & 31) * 4;    // n 0..124

    const float* Ap0 = A  + (size_t)(bm + a_r)      * K + a_c4 * 4;
    const float* Ap1 = A  + (size_t)(bm + 64 + a_r) * K + a_c4 * 4;
    const float* Bp0 = Bm + (size_t)b_k       * N + bn + b_nc;
    const float* Bp1 = Bm + (size_t)(b_k + 8) * N + bn + b_nc;

    // Destination bases (byte offsets within one buffer), k-dependence added
    // at store time via kt.
    // A: value (r, k=4*c4+i): kt=c4>>1, reg=((r>>3)&1)|((c4&1)<<1),
    //    byte = ((r>>4)*2+kt)*512 + (r&7)*64 + i*16 + reg*4
    #define A_BASE(r_, c4_) \
        ((((r_) >> 4) * 2 + ((c4_) >> 1)) * 512 + ((r_) & 7) * 64 + \
         (((((r_) >> 3) & 1) | (((c4_) & 1) << 1)) * 4))
    // B: value (k, n=nc+i): reg=(k>>2)&1,
    //    byte = 8192 + ((nc>>3)*2 + (k>>3))*256 + ((nc&7)*4 + (k&3))*8 + i*32 + reg*4
    #define B_BASE(k_, nc_) \
        (8192 + (((nc_) >> 3) * 2 + ((k_) >> 3)) * 256 + \
         ((((nc_) & 7) * 4 + ((k_) & 3)) * 8) + ((((k_) >> 2) & 1) * 4))

    const int aoff0 = A_BASE(a_r, a_c4);
    const int aoff1 = A_BASE(a_r + 64, a_c4);
    const int boff0 = B_BASE(b_k, b_nc);
    const int boff1 = B_BASE(b_k + 8, b_nc);

    #define STORE_CHUNK(buf, ra0, ra1, rb0, rb1) do {                         \
        char* base = (char*)&sm[buf][0];                                      \
        char* p;                                                              \
        p = base + aoff0;                                                     \
        *(uint32_t*)(p +  0) = f2tf32((ra0).x);                               \
        *(uint32_t*)(p + 16) = f2tf32((ra0).y);                               \
        *(uint32_t*)(p + 32) = f2tf32((ra0).z);                               \
        *(uint32_t*)(p + 48) = f2tf32((ra0).w);                               \
        p = base + aoff1;                                                     \
        *(uint32_t*)(p +  0) = f2tf32((ra1).x);                               \
        *(uint32_t*)(p + 16) = f2tf32((ra1).y);                               \
        *(uint32_t*)(p + 32) = f2tf32((ra1).z);                               \
        *(uint32_t*)(p + 48) = f2tf32((ra1).w);                               \
        p = base + boff0;                                                     \
        *(uint32_t*)(p +  0) = f2tf32((rb0).x);                               \
        *(uint32_t*)(p + 32) = f2tf32((rb0).y);                               \
        *(uint32_t*)(p + 64) = f2tf32((rb0).z);                               \
        *(uint32_t*)(p + 96) = f2tf32((rb0).w);                               \
        p = base + boff1;                                                     \
        *(uint32_t*)(p +  0) = f2tf32((rb1).x);                               \
        *(uint32_t*)(p + 32) = f2tf32((rb1).y);                               \
        *(uint32_t*)(p + 64) = f2tf32((rb1).z);                               \
        *(uint32_t*)(p + 96) = f2tf32((rb1).w);                               \
    } while (0)

    float acc[4][4][4];
#pragma unroll
    for (int mi = 0; mi < 4; mi++)
#pragma unroll
        for (int ni = 0; ni < 4; ni++)
#pragma unroll
            for (int q = 0; q < 4; q++) acc[mi][ni][q] = 0.0f;

    const int nit = K >> 4;

    float4 ra0 = *(const float4*)(Ap0);
    float4 ra1 = *(const float4*)(Ap1);
    float4 rb0 = *(const float4*)(Bp0);
    float4 rb1 = *(const float4*)(Bp1);
    STORE_CHUNK(0, ra0, ra1, rb0, rb1);
    __syncthreads();

    for (int it = 0; it < nit; ++it) {
        const int cur = it & 1;
        const bool more = (it + 1) < nit;

        if (more) {
            const int k0 = (it + 1) << 4;
            ra0 = *(const float4*)(Ap0 + k0);
            ra1 = *(const float4*)(Ap1 + k0);
            rb0 = *(const float4*)(Bp0 + (size_t)k0 * N);
            rb1 = *(const float4*)(Bp1 + (size_t)k0 * N);
        }

        const char* base = (const char*)&sm[cur][0];
#pragma unroll
        for (int ks = 0; ks < 2; ks++) {
            uint32_t af[4][4];
#pragma unroll
            for (int mi = 0; mi < 4; mi++) {
                const uint4 v = *(const uint4*)(base +
                    ((wmt + mi) * 2 + ks) * 512 + lane * 16);
                af[mi][0] = v.x; af[mi][1] = v.y; af[mi][2] = v.z; af[mi][3] = v.w;
            }
            uint32_t bf[4][2];
#pragma unroll
            for (int ni = 0; ni < 4; ni++) {
                const uint2 v = *(const uint2*)(base + 8192 +
                    ((wnt + ni) * 2 + ks) * 256 + lane * 8);
                bf[ni][0] = v.x; bf[ni][1] = v.y;
            }
#pragma unroll
            for (int mi = 0; mi < 4; mi++)
#pragma unroll
                for (int ni = 0; ni < 4; ni++)
                    mma8(acc[mi][ni], af[mi], bf[ni]);
        }

        if (more) {
            STORE_CHUNK(cur ^ 1, ra0, ra1, rb0, rb1);
        }
        __syncthreads();
    }

    // Epilogue
#pragma unroll
    for (int mi = 0; mi < 4; mi++) {
#pragma unroll
        for (int ni = 0; ni < 4; ni++) {
            const int r0 = bm + (wmt + mi) * 16 + lr;
            const int c0 = bn + (wnt + ni) * 8 + lc * 2;
            float b1v0 = bias1 ? bias1[c0]     : 0.0f;
            float b1v1 = bias1 ? bias1[c0 + 1] : 0.0f;
#pragma unroll
            for (int h = 0; h < 2; h++) {
                float x0 = acc[mi][ni][h * 2 + 0] + b1v0;
                float x1 = acc[mi][ni][h * 2 + 1] + b1v1;
                if (EPI == 1) {
                    x0 = tanhf(x0 + bias2[c0]);
                    x1 = tanhf(x1 + bias2[c0 + 1]);
                }
                if (EPI == 2) { x0 = fmaxf(x0, 0.0f); x1 = fmaxf(x1, 0.0f); }
                *(float2*)(C + (size_t)(r0 + h * 8) * N + c0) = make_float2(x0, x1);
            }
        }
    }
    #undef STORE_CHUNK
    #undef A_BASE
    #undef B_BASE
}

// ---------------------------------------------------------------------------
// TF32 MMA GEMM, 64x64 block tile, BK=32, 256 threads, warp tile 32x16.
// (Unchanged from the 182us kernel; small GEMMs only.)
// ---------------------------------------------------------------------------
template<int EPI>
__global__ __launch_bounds__(256) void mma64(
    const float* __restrict__ A, const float* __restrict__ Bm,
    float* __restrict__ C,
    const float* __restrict__ bias1,
    int M, int N, int K)
{
    __shared__ uint32_t As[64][36];
    __shared__ uint32_t Bs[32][72];

    const int tid  = threadIdx.x;
    const int warp = tid >> 5;
    const int lane = tid & 31;
    const int wm   = (warp >> 2) * 32;
    const int wn   = (warp & 3) * 16;
    const int bm   = blockIdx.y * 64;
    const int bn   = blockIdx.x * 64;
    const int lr   = lane >> 2;
    const int lc   = lane & 3;

    float acc[2][2][4];
#pragma unroll
    for (int mi = 0; mi < 2; mi++)
#pragma unroll
        for (int ni = 0; ni < 2; ni++)
#pragma unroll
            for (int q = 0; q < 4; q++) acc[mi][ni][q] = 0.0f;

    for (int k0 = 0; k0 < K; k0 += 32) {
#pragma unroll
        for (int it = 0; it < 2; it++) {
            const int idx = it * 256 + tid;
            const int r  = idx >> 3;
            const int kq = (idx & 7) * 4;
            float4 v = *(const float4*)(A + (size_t)(bm + r) * K + k0 + kq);
            As[r][kq + 0] = f2tf32(v.x);
            As[r][kq + 1] = f2tf32(v.y);
            As[r][kq + 2] = f2tf32(v.z);
            As[r][kq + 3] = f2tf32(v.w);
        }
#pragma unroll
        for (int it = 0; it < 2; it++) {
            const int idx = it * 256 + tid;
            const int r  = idx >> 4;
            const int cq = (idx & 15) * 4;
            float4 v = *(const float4*)(Bm + (size_t)(k0 + r) * N + bn + cq);
            Bs[r][cq + 0] = f2tf32(v.x);
            Bs[r][cq + 1] = f2tf32(v.y);
            Bs[r][cq + 2] = f2tf32(v.z);
            Bs[r][cq + 3] = f2tf32(v.w);
        }
        __syncthreads();

#pragma unroll
        for (int ks = 0; ks < 4; ks++) {
            const int kb = ks * 8;
            uint32_t af[2][4];
#pragma unroll
            for (int mi = 0; mi < 2; mi++) {
                const int r = wm + mi * 16 + lr;
                const int c = kb + lc;
                af[mi][0] = As[r][c];
                af[mi][1] = As[r + 8][c];
                af[mi][2] = As[r][c + 4];
                af[mi][3] = As[r + 8][c + 4];
            }
            uint32_t bf[2][2];
#pragma unroll
            for (int ni = 0; ni < 2; ni++) {
                const int cc = wn + ni * 8 + lr;
                const int rr = kb + lc;
                bf[ni][0] = Bs[rr][cc];
                bf[ni][1] = Bs[rr + 4][cc];
            }
#pragma unroll
            for (int mi = 0; mi < 2; mi++)
#pragma unroll
                for (int ni = 0; ni < 2; ni++)
                    mma8(acc[mi][ni], af[mi], bf[ni]);
        }
        __syncthreads();
    }

#pragma unroll
    for (int mi = 0; mi < 2; mi++) {
#pragma unroll
        for (int ni = 0; ni < 2; ni++) {
            const int r0 = bm + wm + mi * 16 + lr;
            const int c0 = bn + wn + ni * 8 + lc * 2;
            float b1v0 = bias1 ? bias1[c0]     : 0.0f;
            float b1v1 = bias1 ? bias1[c0 + 1] : 0.0f;
#pragma unroll
            for (int h = 0; h < 2; h++) {
                float x0 = acc[mi][ni][h * 2 + 0] + b1v0;
                float x1 = acc[mi][ni][h * 2 + 1] + b1v1;
                if (EPI == 2) { x0 = fmaxf(x0, 0.0f); x1 = fmaxf(x1, 0.0f); }
                *(float2*)(C + (size_t)(r0 + h * 8) * N + c0) = make_float2(x0, x1);
            }
        }
    }
}

// ---------------------------------------------------------------------------
// Attention reduction: score = E@vW + vb, softmax over S, context; builds xc.
// ---------------------------------------------------------------------------
__global__ __launch_bounds__(256) void attn_reduce(
    const float* __restrict__ attn, const float* __restrict__ vW,
    const float* __restrict__ vb,  const int* __restrict__ inputs,
    const float* __restrict__ emb, float* __restrict__ out_alpha)
{
    __shared__ float sc[SS];
    const int b = blockIdx.x;
    const int tid = threadIdx.x;
    const int warp = tid >> 5;
    const int lane = tid & 31;

#pragma unroll
    for (int q = 0; q < 8; q++) {
        const int s = warp * 8 + q;
        const float* e = g_E + (size_t)(b * SS + s) * UU;
        float acc = 0.0f;
        for (int u = lane; u < UU; u += 32) acc += e[u] * vW[u];
#pragma unroll
        for (int o = 16; o; o >>= 1) acc += __shfl_xor_sync(0xffffffffu, acc, o);
        if (lane == 0) sc[s] = acc + vb[0];
    }
    __syncthreads();

    if (warp == 0) {
        float v0 = sc[lane], v1 = sc[lane + 32];
        float m = fmaxf(v0, v1);
#pragma unroll
        for (int o = 16; o; o >>= 1) m = fmaxf(m, __shfl_xor_sync(0xffffffffu, m, o));
        float e0 = expf(v0 - m), e1 = expf(v1 - m);
        float ssum = e0 + e1;
#pragma unroll
        for (int o = 16; o; o >>= 1) ssum += __shfl_xor_sync(0xffffffffu, ssum, o);
        const float inv = 1.0f / ssum;
        sc[lane]      = e0 * inv;
        sc[lane + 32] = e1 * inv;
        out_alpha[b * SS + lane]      = e0 * inv;
        out_alpha[b * SS + lane + 32] = e1 * inv;
    }
    __syncthreads();

    const int erow = inputs[b];
    for (int u = tid; u < UU; u += 256) {
        float c = 0.0f;
        const float* ap = attn + (size_t)(b * SS) * UU + u;
#pragma unroll 8
        for (int s = 0; s < SS; s++) c += sc[s] * ap[(size_t)s * UU];
        g_xc[b * XCC + UU + u] = c;
        g_xc[b * XCC + u] = emb[(size_t)erow * UU + u];
    }
}

// ---------------------------------------------------------------------------
// GRU gates (h = 0): state = (1-z)*tanh(xh + r*b1h), z/r sigmoid.
// ---------------------------------------------------------------------------
__global__ __launch_bounds__(256) void gru_gates(
    const float* __restrict__ gru_b, float* __restrict__ out_state)
{
    const int i = blockIdx.x * blockDim.x + threadIdx.x;
    const int b = i >> 9;
    const int n = i & 511;
    const float* gb1 = gru_b + G3;
    const float* u = g_U + (size_t)b * G3;
    const float xz = u[n]        + gb1[n];
    const float xr = u[512 + n]  + gb1[512 + n];
    const float xh = u[1024 + n];
    const float z = 1.0f / (1.0f + expf(-xz));
    const float r = 1.0f / (1.0f + expf(-xr));
    const float hh = tanhf(xh + r * gb1[1024 + n]);
    out_state[i] = (1.0f - z) * hh;
}

// ---------------------------------------------------------------------------
extern "C" void kernel_launch(void* const* d_in, const int* in_sizes, int n_in,
                              void* d_out, int out_size)
{
    (void)in_sizes; (void)n_in; (void)out_size;

    const int*   inputs = (const int*)  d_in[0];
    const float* attn   = (const float*)d_in[1];
    const float* W0     = (const float*)d_in[2];
    const float* b0     = (const float*)d_in[3];
    // d_in[4] = W1 (unused: hidden0 == 0)
    const float* b1     = (const float*)d_in[5];
    const float* vW     = (const float*)d_in[6];
    const float* vb     = (const float*)d_in[7];
    const float* emb    = (const float*)d_in[8];
    const float* gru_k  = (const float*)d_in[9];
    // d_in[10] = gru_rk (unused: h == 0)
    const float* gru_b  = (const float*)d_in[11];
    const float* dW     = (const float*)d_in[12];
    const float* db     = (const float*)d_in[13];
    const float* oW     = (const float*)d_in[14];
    const float* ob     = (const float*)d_in[15];
    float* out = (float*)d_out;

    float *pE, *pXC, *pU, *pY;
    cudaGetSymbolAddress((void**)&pE,  g_E);
    cudaGetSymbolAddress((void**)&pXC, g_xc);
    cudaGetSymbolAddress((void**)&pU,  g_U);
    cudaGetSymbolAddress((void**)&pY,  g_y);

    // 1) E = tanh(attn2d @ W0 + b0 + b1)   [8192 x 512 x 512]
    mma128f<1><<<dim3(UU/128, (BB*SS)/128), 256>>>(attn, W0, pE, b0, b1,
                                                   BB*SS, UU, UU);
    // 2) score -> softmax -> alpha(out) -> context; build xc
    attn_reduce<<<BB, 256>>>(attn, vW, vb, inputs, emb, out + ALPHA_OFF);

    // 3) U = xc @ gru_k + gru_b[0]          [128 x 1536 x 1024]
    mma64<0><<<dim3(G3/64, BB/64), 256>>>(pXC, gru_k, pU, gru_b,
                                          BB, G3, XCC);
    // 4) gates -> state (straight into d_out)
    gru_gates<<<(BB*UU)/256, 256>>>(gru_b, out + STATE_OFF);

    // 5) y = relu(state @ dW + db)          [128 x 512 x 512]
    mma64<2><<<dim3(UU/64, BB/64), 256>>>(out + STATE_OFF, dW, pY, db,
                                          BB, UU, UU);
    // 6) logits = y @ oW + ob               [128 x 32000 x 512]
    mma128f<0><<<dim3(VV/128, BB/128), 256>>>(pY, oW, out, ob, nullptr,
                                              BB, VV, UU);
}

// round 8
// speedup vs baseline: 1.8827x; 1.8827x over previous
#include <cuda_runtime.h>
#include <cuda_fp16.h>
#include <math.h>
#include <stdint.h>

// Problem dims
#define BB 128
#define SS 64
#define UU 512
#define VV 32000
#define XCC 1024   // 2U
#define G3 1536    // 3U

// Output layout: [logits (128*32000)] [state (128*512)] [alpha (128*64)]
#define STATE_OFF (BB*VV)
#define ALPHA_OFF (BB*VV + BB*UU)

// Scratch (device globals: allocation-free)
__device__ float g_E[BB*SS*UU];   // tanh(attn@W0+b0+b1)
__device__ float g_xc[BB*XCC];    // [emb gather | context]
__device__ float g_U[BB*G3];      // xc@gru_k + gru_b[0]
__device__ float g_y[BB*UU];      // relu(state@dW+db)

__device__ __forceinline__ uint32_t f2tf32(float x) {
    uint32_t r; asm("cvt.rna.tf32.f32 %0, %1;" : "=r"(r) : "f"(x)); return r;
}

__device__ __forceinline__ uint32_t packh(float a, float b) {
    __half2 v;
    v.x = __float2half_rn(a);
    v.y = __float2half_rn(b);
    return *(uint32_t*)&v;
}

__device__ __forceinline__ void mma8(float* c, const uint32_t* a, const uint32_t* b) {
    asm volatile(
        "mma.sync.aligned.m16n8k8.row.col.f32.tf32.tf32.f32 "
        "{%0,%1,%2,%3},{%4,%5,%6,%7},{%8,%9},{%0,%1,%2,%3};"
        : "+f"(c[0]), "+f"(c[1]), "+f"(c[2]), "+f"(c[3])
        : "r"(a[0]), "r"(a[1]), "r"(a[2]), "r"(a[3]),
          "r"(b[0]), "r"(b[1]));
}

__device__ __forceinline__ void mma16h(float* c, const uint32_t* a, const uint32_t* b) {
    asm volatile(
        "mma.sync.aligned.m16n8k16.row.col.f32.f16.f16.f32 "
        "{%0,%1,%2,%3},{%4,%5,%6,%7},{%8,%9},{%0,%1,%2,%3};"
        : "+f"(c[0]), "+f"(c[1]), "+f"(c[2]), "+f"(c[3])
        : "r"(a[0]), "r"(a[1]), "r"(a[2]), "r"(a[3]),
          "r"(b[0]), "r"(b[1]));
}

// ---------------------------------------------------------------------------
// FP16 mma.sync GEMM (m16n8k16), 128x128 block, BK=32, 256 threads (8 warps
// 2x4), warp tile 64x32. R2-style loop: fill -> sync -> compute -> sync.
// SMEM (half2 words):
//   As2[r][k2], stride 20: compute loads conflict-free
//   Bs2[n][k2], stride 17: B transposed at fill (k-pair packed in half2)
// C = epi(A[M,K]@B[K,N] + bias1 (+bias2)). EPI: 0 bias, 1 +bias2/tanh, 2 relu.
// Requires M%128==0, N%128==0, K%32==0.
// ---------------------------------------------------------------------------
template<int EPI>
__global__ __launch_bounds__(256) void mma128h(
    const float* __restrict__ A, const float* __restrict__ Bm,
    float* __restrict__ C,
    const float* __restrict__ bias1, const float* __restrict__ bias2,
    int M, int N, int K)
{
    __shared__ uint32_t As2[128][20];   // k2 = 0..15 used
    __shared__ uint32_t Bs2[128][17];   // k2 = 0..15 used

    const int tid  = threadIdx.x;
    const int warp = tid >> 5;
    const int lane = tid & 31;
    const int bm   = blockIdx.y * 128;
    const int bn   = blockIdx.x * 128;
    const int wm   = (warp >> 2) * 64;   // warp row offset
    const int wn   = (warp & 3) * 32;    // warp col offset
    const int lr   = lane >> 2;          // 0..7
    const int lc   = lane & 3;           // 0..3

    // A fill: row a_r, halves (tid&1)*16 .. +15  (4 float4 loads, 8 half2 STS)
    const int a_r  = tid >> 1;           // 0..127
    const int a_h  = (tid & 1) * 16;     // half (k) offset
    // B fill: kpairs kp & kp+8, columns b_n4..b_n4+3 (transpose in registers)
    const int b_kp = tid >> 5;           // 0..7
    const int b_n4 = (tid & 31) * 4;     // 0..124

    float acc[4][4][4];
#pragma unroll
    for (int mi = 0; mi < 4; mi++)
#pragma unroll
        for (int ni = 0; ni < 4; ni++)
#pragma unroll
            for (int q = 0; q < 4; q++) acc[mi][ni][q] = 0.0f;

    for (int k0 = 0; k0 < K; k0 += 32) {
        // ---- fill A (128x32 halves) ----
#pragma unroll
        for (int j = 0; j < 4; j++) {
            float4 v = *(const float4*)(A + (size_t)(bm + a_r) * K + k0 + a_h + j * 4);
            As2[a_r][(a_h >> 1) + j * 2 + 0] = packh(v.x, v.y);
            As2[a_r][(a_h >> 1) + j * 2 + 1] = packh(v.z, v.w);
        }
        // ---- fill B transposed (32k x 128n -> Bs2[n][k2]) ----
#pragma unroll
        for (int j = 0; j < 2; j++) {
            const int kp = b_kp + j * 8;                  // k-pair index 0..15
            float4 f0 = *(const float4*)(Bm + (size_t)(k0 + 2 * kp)     * N + bn + b_n4);
            float4 f1 = *(const float4*)(Bm + (size_t)(k0 + 2 * kp + 1) * N + bn + b_n4);
            Bs2[b_n4 + 0][kp] = packh(f0.x, f1.x);
            Bs2[b_n4 + 1][kp] = packh(f0.y, f1.y);
            Bs2[b_n4 + 2][kp] = packh(f0.z, f1.z);
            Bs2[b_n4 + 3][kp] = packh(f0.w, f1.w);
        }
        __syncthreads();

        // ---- compute: 2 k16 slices ----
#pragma unroll
        for (int ks = 0; ks < 2; ks++) {
            const int kq = ks * 8;       // half2 base
            uint32_t af[4][4];
#pragma unroll
            for (int mi = 0; mi < 4; mi++) {
                const int r = wm + mi * 16 + lr;
                af[mi][0] = As2[r][kq + lc];
                af[mi][1] = As2[r + 8][kq + lc];
                af[mi][2] = As2[r][kq + 4 + lc];
                af[mi][3] = As2[r + 8][kq + 4 + lc];
            }
            uint32_t bf[4][2];
#pragma unroll
            for (int ni = 0; ni < 4; ni++) {
                const int cc = wn + ni * 8 + lr;
                bf[ni][0] = Bs2[cc][kq + lc];
                bf[ni][1] = Bs2[cc][kq + 4 + lc];
            }
#pragma unroll
            for (int mi = 0; mi < 4; mi++)
#pragma unroll
                for (int ni = 0; ni < 4; ni++)
                    mma16h(acc[mi][ni], af[mi], bf[ni]);
        }
        __syncthreads();
    }

    // Epilogue
#pragma unroll
    for (int mi = 0; mi < 4; mi++) {
#pragma unroll
        for (int ni = 0; ni < 4; ni++) {
            const int r0 = bm + wm + mi * 16 + lr;
            const int c0 = bn + wn + ni * 8 + lc * 2;
            float b1v0 = bias1 ? bias1[c0]     : 0.0f;
            float b1v1 = bias1 ? bias1[c0 + 1] : 0.0f;
#pragma unroll
            for (int h = 0; h < 2; h++) {
                float x0 = acc[mi][ni][h * 2 + 0] + b1v0;
                float x1 = acc[mi][ni][h * 2 + 1] + b1v1;
                if (EPI == 1) {
                    x0 = tanhf(x0 + bias2[c0]);
                    x1 = tanhf(x1 + bias2[c0 + 1]);
                }
                if (EPI == 2) { x0 = fmaxf(x0, 0.0f); x1 = fmaxf(x1, 0.0f); }
                *(float2*)(C + (size_t)(r0 + h * 8) * N + c0) = make_float2(x0, x1);
            }
        }
    }
}

// ---------------------------------------------------------------------------
// TF32 MMA GEMM, 64x64 block tile, BK=32, 256 threads, warp tile 32x16.
// (Proven; small GEMMs only.)
// ---------------------------------------------------------------------------
template<int EPI>
__global__ __launch_bounds__(256) void mma64(
    const float* __restrict__ A, const float* __restrict__ Bm,
    float* __restrict__ C,
    const float* __restrict__ bias1,
    int M, int N, int K)
{
    __shared__ uint32_t As[64][36];
    __shared__ uint32_t Bs[32][72];

    const int tid  = threadIdx.x;
    const int warp = tid >> 5;
    const int lane = tid & 31;
    const int wm   = (warp >> 2) * 32;
    const int wn   = (warp & 3) * 16;
    const int bm   = blockIdx.y * 64;
    const int bn   = blockIdx.x * 64;
    const int lr   = lane >> 2;
    const int lc   = lane & 3;

    float acc[2][2][4];
#pragma unroll
    for (int mi = 0; mi < 2; mi++)
#pragma unroll
        for (int ni = 0; ni < 2; ni++)
#pragma unroll
            for (int q = 0; q < 4; q++) acc[mi][ni][q] = 0.0f;

    for (int k0 = 0; k0 < K; k0 += 32) {
#pragma unroll
        for (int it = 0; it < 2; it++) {
            const int idx = it * 256 + tid;
            const int r  = idx >> 3;
            const int kq = (idx & 7) * 4;
            float4 v = *(const float4*)(A + (size_t)(bm + r) * K + k0 + kq);
            As[r][kq + 0] = f2tf32(v.x);
            As[r][kq + 1] = f2tf32(v.y);
            As[r][kq + 2] = f2tf32(v.z);
            As[r][kq + 3] = f2tf32(v.w);
        }
#pragma unroll
        for (int it = 0; it < 2; it++) {
            const int idx = it * 256 + tid;
            const int r  = idx >> 4;
            const int cq = (idx & 15) * 4;
            float4 v = *(const float4*)(Bm + (size_t)(k0 + r) * N + bn + cq);
            Bs[r][cq + 0] = f2tf32(v.x);
            Bs[r][cq + 1] = f2tf32(v.y);
            Bs[r][cq + 2] = f2tf32(v.z);
            Bs[r][cq + 3] = f2tf32(v.w);
        }
        __syncthreads();

#pragma unroll
        for (int ks = 0; ks < 4; ks++) {
            const int kb = ks * 8;
            uint32_t af[2][4];
#pragma unroll
            for (int mi = 0; mi < 2; mi++) {
                const int r = wm + mi * 16 + lr;
                const int c = kb + lc;
                af[mi][0] = As[r][c];
                af[mi][1] = As[r + 8][c];
                af[mi][2] = As[r][c + 4];
                af[mi][3] = As[r + 8][c + 4];
            }
            uint32_t bf[2][2];
#pragma unroll
            for (int ni = 0; ni < 2; ni++) {
                const int cc = wn + ni * 8 + lr;
                const int rr = kb + lc;
                bf[ni][0] = Bs[rr][cc];
                bf[ni][1] = Bs[rr + 4][cc];
            }
#pragma unroll
            for (int mi = 0; mi < 2; mi++)
#pragma unroll
                for (int ni = 0; ni < 2; ni++)
                    mma8(acc[mi][ni], af[mi], bf[ni]);
        }
        __syncthreads();
    }

#pragma unroll
    for (int mi = 0; mi < 2; mi++) {
#pragma unroll
        for (int ni = 0; ni < 2; ni++) {
            const int r0 = bm + wm + mi * 16 + lr;
            const int c0 = bn + wn + ni * 8 + lc * 2;
            float b1v0 = bias1 ? bias1[c0]     : 0.0f;
            float b1v1 = bias1 ? bias1[c0 + 1] : 0.0f;
#pragma unroll
            for (int h = 0; h < 2; h++) {
                float x0 = acc[mi][ni][h * 2 + 0] + b1v0;
                float x1 = acc[mi][ni][h * 2 + 1] + b1v1;
                if (EPI == 2) { x0 = fmaxf(x0, 0.0f); x1 = fmaxf(x1, 0.0f); }
                *(float2*)(C + (size_t)(r0 + h * 8) * N + c0) = make_float2(x0, x1);
            }
        }
    }
}

// ---------------------------------------------------------------------------
// Attention reduction: score = E@vW + vb, softmax over S, context; builds xc.
// ---------------------------------------------------------------------------
__global__ __launch_bounds__(256) void attn_reduce(
    const float* __restrict__ attn, const float* __restrict__ vW,
    const float* __restrict__ vb,  const int* __restrict__ inputs,
    const float* __restrict__ emb, float* __restrict__ out_alpha)
{
    __shared__ float sc[SS];
    const int b = blockIdx.x;
    const int tid = threadIdx.x;
    const int warp = tid >> 5;
    const int lane = tid & 31;

#pragma unroll
    for (int q = 0; q < 8; q++) {
        const int s = warp * 8 + q;
        const float* e = g_E + (size_t)(b * SS + s) * UU;
        float acc = 0.0f;
        for (int u = lane; u < UU; u += 32) acc += e[u] * vW[u];
#pragma unroll
        for (int o = 16; o; o >>= 1) acc += __shfl_xor_sync(0xffffffffu, acc, o);
        if (lane == 0) sc[s] = acc + vb[0];
    }
    __syncthreads();

    if (warp == 0) {
        float v0 = sc[lane], v1 = sc[lane + 32];
        float m = fmaxf(v0, v1);
#pragma unroll
        for (int o = 16; o; o >>= 1) m = fmaxf(m, __shfl_xor_sync(0xffffffffu, m, o));
        float e0 = expf(v0 - m), e1 = expf(v1 - m);
        float ssum = e0 + e1;
#pragma unroll
        for (int o = 16; o; o >>= 1) ssum += __shfl_xor_sync(0xffffffffu, ssum, o);
        const float inv = 1.0f / ssum;
        sc[lane]      = e0 * inv;
        sc[lane + 32] = e1 * inv;
        out_alpha[b * SS + lane]      = e0 * inv;
        out_alpha[b * SS + lane + 32] = e1 * inv;
    }
    __syncthreads();

    const int erow = inputs[b];
    for (int u = tid; u < UU; u += 256) {
        float c = 0.0f;
        const float* ap = attn + (size_t)(b * SS) * UU + u;
#pragma unroll 8
        for (int s = 0; s < SS; s++) c += sc[s] * ap[(size_t)s * UU];
        g_xc[b * XCC + UU + u] = c;
        g_xc[b * XCC + u] = emb[(size_t)erow * UU + u];
    }
}

// ---------------------------------------------------------------------------
// GRU gates (h = 0): state = (1-z)*tanh(xh + r*b1h), z/r sigmoid.
// ---------------------------------------------------------------------------
__global__ __launch_bounds__(256) void gru_gates(
    const float* __restrict__ gru_b, float* __restrict__ out_state)
{
    const int i = blockIdx.x * blockDim.x + threadIdx.x;
    const int b = i >> 9;
    const int n = i & 511;
    const float* gb1 = gru_b + G3;
    const float* u = g_U + (size_t)b * G3;
    const float xz = u[n]        + gb1[n];
    const float xr = u[512 + n]  + gb1[512 + n];
    const float xh = u[1024 + n];
    const float z = 1.0f / (1.0f + expf(-xz));
    const float r = 1.0f / (1.0f + expf(-xr));
    const float hh = tanhf(xh + r * gb1[1024 + n]);
    out_state[i] = (1.0f - z) * hh;
}

// ---------------------------------------------------------------------------
extern "C" void kernel_launch(void* const* d_in, const int* in_sizes, int n_in,
                              void* d_out, int out_size)
{
    (void)in_sizes; (void)n_in; (void)out_size;

    const int*   inputs = (const int*)  d_in[0];
    const float* attn   = (const float*)d_in[1];
    const float* W0     = (const float*)d_in[2];
    const float* b0     = (const float*)d_in[3];
    // d_in[4] = W1 (unused: hidden0 == 0)
    const float* b1     = (const float*)d_in[5];
    const float* vW     = (const float*)d_in[6];
    const float* vb     = (const float*)d_in[7];
    const float* emb    = (const float*)d_in[8];
    const float* gru_k  = (const float*)d_in[9];
    // d_in[10] = gru_rk (unused: h == 0)
    const float* gru_b  = (const float*)d_in[11];
    const float* dW     = (const float*)d_in[12];
    const float* db     = (const float*)d_in[13];
    const float* oW     = (const float*)d_in[14];
    const float* ob     = (const float*)d_in[15];
    float* out = (float*)d_out;

    float *pE, *pXC, *pU, *pY;
    cudaGetSymbolAddress((void**)&pE,  g_E);
    cudaGetSymbolAddress((void**)&pXC, g_xc);
    cudaGetSymbolAddress((void**)&pU,  g_U);
    cudaGetSymbolAddress((void**)&pY,  g_y);

    // 1) E = tanh(attn2d @ W0 + b0 + b1)   [8192 x 512 x 512]  fp16 tensor
    mma128h<1><<<dim3(UU/128, (BB*SS)/128), 256>>>(attn, W0, pE, b0, b1,
                                                   BB*SS, UU, UU);
    // 2) score -> softmax -> alpha(out) -> context; build xc
    attn_reduce<<<BB, 256>>>(attn, vW, vb, inputs, emb, out + ALPHA_OFF);

    // 3) U = xc @ gru_k + gru_b[0]          [128 x 1536 x 1024] tf32 tensor
    mma64<0><<<dim3(G3/64, BB/64), 256>>>(pXC, gru_k, pU, gru_b,
                                          BB, G3, XCC);
    // 4) gates -> state (straight into d_out)
    gru_gates<<<(BB*UU)/256, 256>>>(gru_b, out + STATE_OFF);

    // 5) y = relu(state @ dW + db)          [128 x 512 x 512] tf32 tensor
    mma64<2><<<dim3(UU/64, BB/64), 256>>>(out + STATE_OFF, dW, pY, db,
                                          BB, UU, UU);
    // 6) logits = y @ oW + ob               [128 x 32000 x 512] fp16 tensor
    mma128h<0><<<dim3(VV/128, BB/128), 256>>>(pY, oW, out, ob, nullptr,
                                              BB, VV, UU);
}